// round 1
// baseline (speedup 1.0000x reference)
#include <cuda_runtime.h>
#include <cstdint>

#define N_MAX 50000
#define E_MAX 640000
#define D 128
#define ROWLEN 129
#define EPSV 1e-9f
#define WMIN 1e-6f

// ---- static scratch (no allocation allowed) ----
__device__ float g_norms[N_MAX];
__device__ int   g_deg[N_MAX];
__device__ int   g_cursor[N_MAX];
__device__ int   g_rowptr[N_MAX + 1];
__device__ int   g_col[E_MAX];
__device__ float g_neigh[(size_t)N_MAX * D];

// ---------------------------------------------------------------- zero counts
__global__ void zero_kernel(int N) {
    int i = blockIdx.x * blockDim.x + threadIdx.x;
    if (i < N) { g_deg[i] = 0; g_cursor[i] = 0; }
}

// ---------------------------------------------------------------- feature norms (warp per row)
__global__ void norms_kernel(const float* __restrict__ x, int N) {
    int warp = (blockIdx.x * blockDim.x + threadIdx.x) >> 5;
    int lane = threadIdx.x & 31;
    if (warp >= N) return;
    const float* xr = x + (size_t)warp * ROWLEN;
    float a0 = xr[lane], a1 = xr[lane + 32], a2 = xr[lane + 64], a3 = xr[lane + 96];
    float s = a0 * a0 + a1 * a1 + a2 * a2 + a3 * a3;
#pragma unroll
    for (int off = 16; off > 0; off >>= 1) s += __shfl_xor_sync(0xffffffffu, s, off);
    if (lane == 0) g_norms[warp] = s;
}

// ---------------------------------------------------------------- degree histogram
__global__ void hist_kernel(const int* __restrict__ ei, int E) {
    int e = blockIdx.x * blockDim.x + threadIdx.x;
    if (e < E) atomicAdd(&g_deg[ei[e]], 1);
}

// ---------------------------------------------------------------- exclusive scan (single block)
__global__ void scan_kernel(int N) {
    __shared__ int wsum[32];
    __shared__ int carry;
    int tid = threadIdx.x, lane = tid & 31, wid = tid >> 5;
    if (tid == 0) { carry = 0; g_rowptr[0] = 0; }
    __syncthreads();
    for (int base = 0; base < N; base += 1024) {
        int i = base + tid;
        int v = (i < N) ? g_deg[i] : 0;
        int s = v;
#pragma unroll
        for (int off = 1; off < 32; off <<= 1) {
            int t = __shfl_up_sync(0xffffffffu, s, off);
            if (lane >= off) s += t;
        }
        if (lane == 31) wsum[wid] = s;
        __syncthreads();
        if (wid == 0) {
            int ws = wsum[lane];
#pragma unroll
            for (int off = 1; off < 32; off <<= 1) {
                int t = __shfl_up_sync(0xffffffffu, ws, off);
                if (lane >= off) ws += t;
            }
            wsum[lane] = ws;
        }
        __syncthreads();
        int incl = carry + s + (wid > 0 ? wsum[wid - 1] : 0);
        if (i < N) g_rowptr[i + 1] = incl;
        __syncthreads();
        if (tid == 0) carry += wsum[31];
        __syncthreads();
    }
}

// ---------------------------------------------------------------- scatter edges into CSR
__global__ void scatter_kernel(const int* __restrict__ ei, int E) {
    int e = blockIdx.x * blockDim.x + threadIdx.x;
    if (e < E) {
        int r = ei[e];
        int c = ei[E + e];
        int p = atomicAdd(&g_cursor[r], 1);
        g_col[g_rowptr[r] + p] = c;
    }
}

// ---------------------------------------------------------------- aggregation (warp per row)
// Computes per-edge weight w = exp(dot^2/((nr+eps)(nc+eps)) - 1) and the
// normalized weighted neighbor mean, all in registers. One 516B gather per edge.
__global__ void agg_kernel(const float* __restrict__ x, int N) {
    int warp = (blockIdx.x * blockDim.x + threadIdx.x) >> 5;
    int lane = threadIdx.x & 31;
    if (warp >= N) return;
    int r = warp;
    const float* xr = x + (size_t)r * ROWLEN;
    float xr0 = xr[lane], xr1 = xr[lane + 32], xr2 = xr[lane + 64], xr3 = xr[lane + 96];
    float xrh = xr[128];                    // broadcast load (same addr all lanes)
    float nr = g_norms[r] + EPSV;
    float acc0 = 0.f, acc1 = 0.f, acc2 = 0.f, acc3 = 0.f, wsum = 0.f;
    int jb = g_rowptr[r], je = g_rowptr[r + 1];
#pragma unroll 2
    for (int j = jb; j < je; j++) {
        int c = g_col[j];
        const float* xc = x + (size_t)c * ROWLEN;
        float c0 = xc[lane], c1 = xc[lane + 32], c2 = xc[lane + 64], c3 = xc[lane + 96];
        float part = xr0 * c0 + xr1 * c1 + xr2 * c2 + xr3 * c3;
        if (lane == 0) part += xrh * xc[128];
#pragma unroll
        for (int off = 16; off > 0; off >>= 1) part += __shfl_xor_sync(0xffffffffu, part, off);
        float nc = g_norms[c] + EPSV;
        float w = __expf(part * part / (nr * nc) - 1.0f);
        acc0 += w * c0; acc1 += w * c1; acc2 += w * c2; acc3 += w * c3;
        wsum += w;
    }
    float inv = 1.0f / fmaxf(wsum, WMIN);
    float* nout = g_neigh + (size_t)r * D;
    nout[lane]      = acc0 * inv;
    nout[lane + 32] = acc1 * inv;
    nout[lane + 64] = acc2 * inv;
    nout[lane + 96] = acc3 * inv;
}

// ---------------------------------------------------------------- fused GEMM + relu + concat
// out[r, 0:128] = relu( neigh[r,:] @ Wn^T + feat[r,:] @ Ws^T ), out[r,128] = relu(x[r,128])
// Treated as a single 50000x128x256 GEMM: A = [neigh | feat], B = [Wn | Ws] (row j holds Wn[j,:],Ws[j,:]).
// Tile: 64 rows x 128 cols per 256-thread CTA, K-chunks of 32, 4x8 micro-tile.
__global__ __launch_bounds__(256) void gemm_kernel(
    const float* __restrict__ x, const float* __restrict__ Wn,
    const float* __restrict__ Ws, float* __restrict__ out, int N)
{
    __shared__ float As[32][68];    // [k][row], 68-pad keeps rows 16B aligned, low conflicts
    __shared__ float Bs[32][132];   // [k][col]
    int t  = threadIdx.x;
    int tx = t & 15;        // cols tx*8 .. tx*8+7
    int ty = t >> 4;        // rows ty*4 .. ty*4+3
    int row0 = blockIdx.x * 64;

    float acc[4][8];
#pragma unroll
    for (int i = 0; i < 4; i++)
#pragma unroll
        for (int j = 0; j < 8; j++) acc[i][j] = 0.f;

    for (int kk = 0; kk < 256; kk += 32) {
        // load A tile: 64x32 (consecutive threads -> consecutive k: coalesced global reads)
#pragma unroll
        for (int i = 0; i < 8; i++) {
            int idx = t + i * 256;          // 0..2047
            int rr  = idx >> 5;
            int k   = idx & 31;
            int kg  = kk + k;
            int r   = row0 + rr;
            float v = 0.f;
            if (r < N)
                v = (kg < 128) ? g_neigh[(size_t)r * D + kg]
                               : x[(size_t)r * ROWLEN + (kg - 128)];
            As[k][rr] = v;
        }
        // load B tile: 128x32
#pragma unroll
        for (int i = 0; i < 16; i++) {
            int idx = t + i * 256;          // 0..4095
            int jj  = idx >> 5;
            int k   = idx & 31;
            int kg  = kk + k;
            float v = (kg < 128) ? Wn[jj * 128 + kg] : Ws[jj * 128 + (kg - 128)];
            Bs[k][jj] = v;
        }
        __syncthreads();
#pragma unroll
        for (int k = 0; k < 32; k++) {
            float4 a  = *(const float4*)&As[k][ty * 4];
            float4 b0 = *(const float4*)&Bs[k][tx * 8];
            float4 b1 = *(const float4*)&Bs[k][tx * 8 + 4];
            float av[4] = {a.x, a.y, a.z, a.w};
            float bv[8] = {b0.x, b0.y, b0.z, b0.w, b1.x, b1.y, b1.z, b1.w};
#pragma unroll
            for (int i = 0; i < 4; i++)
#pragma unroll
                for (int j = 0; j < 8; j++) acc[i][j] += av[i] * bv[j];
        }
        __syncthreads();
    }

#pragma unroll
    for (int i = 0; i < 4; i++) {
        int r = row0 + ty * 4 + i;
        if (r < N) {
            float* orow = out + (size_t)r * ROWLEN + tx * 8;
#pragma unroll
            for (int j = 0; j < 8; j++) orow[j] = fmaxf(acc[i][j], 0.f);
        }
    }
    if (t < 64) {
        int r = row0 + t;
        if (r < N) out[(size_t)r * ROWLEN + 128] = fmaxf(x[(size_t)r * ROWLEN + 128], 0.f);
    }
}

// ---------------------------------------------------------------- launch
extern "C" void kernel_launch(void* const* d_in, const int* in_sizes, int n_in,
                              void* d_out, int out_size) {
    const float* x  = (const float*)d_in[0];
    const int*   ei = (const int*)d_in[1];
    const float* Wn = (const float*)d_in[2];
    const float* Ws = (const float*)d_in[3];
    float* out = (float*)d_out;
    int N = in_sizes[0] / ROWLEN;
    int E = in_sizes[1] / 2;

    zero_kernel<<<(N + 255) / 256, 256>>>(N);
    norms_kernel<<<(N + 7) / 8, 256>>>(x, N);
    hist_kernel<<<(E + 255) / 256, 256>>>(ei, E);
    scan_kernel<<<1, 1024>>>(N);
    scatter_kernel<<<(E + 255) / 256, 256>>>(ei, E);
    agg_kernel<<<(N + 7) / 8, 256>>>(x, N);
    gemm_kernel<<<(N + 63) / 64, 256>>>(x, Wn, Ws, out, N);
}

// round 4
// speedup vs baseline: 1.6925x; 1.6925x over previous
#include <cuda_runtime.h>
#include <cuda_bf16.h>
#include <cstdint>

#define N_MAX 50000
#define E_MAX 640000
#define D 128
#define ROWLEN 129
#define EPSV 1e-9f
#define WMIN 1e-6f

// ---- static scratch ----
__device__ float g_norms[N_MAX];
__device__ int   g_deg[N_MAX];
__device__ int   g_cursor[N_MAX];
__device__ int   g_rowptr[N_MAX + 1];
__device__ int   g_col[E_MAX];
__device__ int   g_part[256];
// A = [neigh | feat] as double-bf16 split (hi, lo), row-major [N][256]
__device__ unsigned short g_Ah[(size_t)N_MAX * 256];
__device__ unsigned short g_Al[(size_t)N_MAX * 256];
// B rows j: [Wn[j,:] | Ws[j,:]] as split, [128][256]
__device__ unsigned short g_Bh[128 * 256];
__device__ unsigned short g_Bl[128 * 256];

__device__ __forceinline__ void split_bf16(float v, unsigned short& h, unsigned short& l) {
    __nv_bfloat16 hb = __float2bfloat16(v);
    float lo = v - __bfloat162float(hb);
    h = __bfloat16_as_ushort(hb);
    l = __bfloat16_as_ushort(__float2bfloat16(lo));
}

// ============================ small kernels ============================
__global__ void zero_kernel(int N) {
    int i = blockIdx.x * blockDim.x + threadIdx.x;
    if (i < N) { g_deg[i] = 0; g_cursor[i] = 0; }
}

__global__ void norms_kernel(const float* __restrict__ x, int N) {
    int warp = (blockIdx.x * blockDim.x + threadIdx.x) >> 5;
    int lane = threadIdx.x & 31;
    if (warp >= N) return;
    const float* xr = x + (size_t)warp * ROWLEN;
    float a0 = xr[lane], a1 = xr[lane + 32], a2 = xr[lane + 64], a3 = xr[lane + 96];
    float s = a0 * a0 + a1 * a1 + a2 * a2 + a3 * a3;
#pragma unroll
    for (int off = 16; off > 0; off >>= 1) s += __shfl_xor_sync(0xffffffffu, s, off);
    if (lane == 0) g_norms[warp] = s;
}

__global__ void hist_kernel(const int* __restrict__ ei, int E) {
    int e = blockIdx.x * blockDim.x + threadIdx.x;
    if (e < E) atomicAdd(&g_deg[ei[e]], 1);
}

// ---- 3-level scan ----
__global__ void scan_part_kernel(int N) {
    __shared__ int ws[8];
    int t = threadIdx.x, b = blockIdx.x;
    int i = b * 256 + t;
    int v = (i < N) ? g_deg[i] : 0;
#pragma unroll
    for (int off = 16; off > 0; off >>= 1) v += __shfl_xor_sync(0xffffffffu, v, off);
    if ((t & 31) == 0) ws[t >> 5] = v;
    __syncthreads();
    if (t == 0) {
        int s = 0;
#pragma unroll
        for (int w = 0; w < 8; w++) s += ws[w];
        g_part[b] = s;
    }
}

__global__ void scan_mid_kernel(int nblk) {
    __shared__ int ws[8];
    int t = threadIdx.x, lane = t & 31, w = t >> 5;
    int v = (t < nblk) ? g_part[t] : 0;
    int s = v;
#pragma unroll
    for (int off = 1; off < 32; off <<= 1) {
        int u = __shfl_up_sync(0xffffffffu, s, off);
        if (lane >= off) s += u;
    }
    if (lane == 31) ws[w] = s;
    __syncthreads();
    if (w == 0) {
        int p = (lane < 8) ? ws[lane] : 0;
#pragma unroll
        for (int off = 1; off < 8; off <<= 1) {
            int u = __shfl_up_sync(0xffffffffu, p, off);
            if (lane >= off) p += u;
        }
        if (lane < 8) ws[lane] = p;
    }
    __syncthreads();
    int incl = s + (w > 0 ? ws[w - 1] : 0);
    g_part[t] = incl - v;
    if (t == 0) g_rowptr[0] = 0;
}

__global__ void scan_final_kernel(int N) {
    __shared__ int ws[8];
    int t = threadIdx.x, b = blockIdx.x, lane = t & 31, w = t >> 5;
    int i = b * 256 + t;
    int v = (i < N) ? g_deg[i] : 0;
    int s = v;
#pragma unroll
    for (int off = 1; off < 32; off <<= 1) {
        int u = __shfl_up_sync(0xffffffffu, s, off);
        if (lane >= off) s += u;
    }
    if (lane == 31) ws[w] = s;
    __syncthreads();
    if (w == 0) {
        int p = (lane < 8) ? ws[lane] : 0;
#pragma unroll
        for (int off = 1; off < 8; off <<= 1) {
            int u = __shfl_up_sync(0xffffffffu, p, off);
            if (lane >= off) p += u;
        }
        if (lane < 8) ws[lane] = p;
    }
    __syncthreads();
    int incl = s + (w > 0 ? ws[w - 1] : 0);
    if (i < N) g_rowptr[i + 1] = g_part[b] + incl;
}

__global__ void scatter_kernel(const int* __restrict__ ei, int E) {
    int e = blockIdx.x * blockDim.x + threadIdx.x;
    if (e < E) {
        int r = ei[e];
        int c = ei[E + e];
        int p = atomicAdd(&g_cursor[r], 1);
        g_col[g_rowptr[r] + p] = c;
    }
}

// ---- operand pre-conversion ----
__global__ void wconv_kernel(const float* __restrict__ Wn, const float* __restrict__ Ws) {
    int j = blockIdx.x, k = threadIdx.x;
    float v = (k < 128) ? Wn[j * 128 + k] : Ws[j * 128 + (k - 128)];
    split_bf16(v, g_Bh[j * 256 + k], g_Bl[j * 256 + k]);
}

__global__ void featconv_kernel(const float* __restrict__ x, int N) {
    int idx = blockIdx.x * blockDim.x + threadIdx.x;
    if (idx >= N * 128) return;
    int r = idx >> 7, k = idx & 127;
    float v = x[(size_t)r * ROWLEN + k];
    split_bf16(v, g_Ah[(size_t)r * 256 + 128 + k], g_Al[(size_t)r * 256 + 128 + k]);
}

// ============================ aggregation (warp per row) ============================
__global__ void agg_kernel(const float* __restrict__ x, int N) {
    int warp = (blockIdx.x * blockDim.x + threadIdx.x) >> 5;
    int lane = threadIdx.x & 31;
    if (warp >= N) return;
    int r = warp;
    const float* xr = x + (size_t)r * ROWLEN;
    float xr0 = xr[lane], xr1 = xr[lane + 32], xr2 = xr[lane + 64], xr3 = xr[lane + 96];
    float xrh = xr[128];
    float nr = g_norms[r] + EPSV;
    float acc0 = 0.f, acc1 = 0.f, acc2 = 0.f, acc3 = 0.f, wsum = 0.f;
    int jb = g_rowptr[r], je = g_rowptr[r + 1];
#pragma unroll 2
    for (int j = jb; j < je; j++) {
        int c = g_col[j];
        const float* xc = x + (size_t)c * ROWLEN;
        float c0 = xc[lane], c1 = xc[lane + 32], c2 = xc[lane + 64], c3 = xc[lane + 96];
        float part = xr0 * c0 + xr1 * c1 + xr2 * c2 + xr3 * c3;
        if (lane == 0) part += xrh * xc[128];
#pragma unroll
        for (int off = 16; off > 0; off >>= 1) part += __shfl_xor_sync(0xffffffffu, part, off);
        float nc = g_norms[c] + EPSV;
        float w = __expf(part * part / (nr * nc) - 1.0f);
        acc0 += w * c0; acc1 += w * c1; acc2 += w * c2; acc3 += w * c3;
        wsum += w;
    }
    float inv = 1.0f / fmaxf(wsum, WMIN);
    size_t base = (size_t)r * 256;
    split_bf16(acc0 * inv, g_Ah[base + lane],      g_Al[base + lane]);
    split_bf16(acc1 * inv, g_Ah[base + lane + 32], g_Al[base + lane + 32]);
    split_bf16(acc2 * inv, g_Ah[base + lane + 64], g_Al[base + lane + 64]);
    split_bf16(acc3 * inv, g_Ah[base + lane + 96], g_Al[base + lane + 96]);
}

// ============================ mma.sync bf16 GEMM + relu + concat ============================
// C[N,128] = A[N,256] @ B[128,256]^T via m16n8k16 bf16 HMMA, 3-term double-bf16 split.
// CTA: 64 rows x 128 cols, 8 warps -> warp tile 16x64. K chunks of 32.
__device__ __forceinline__ void mma_bf16(float* c, uint32_t a0, uint32_t a1, uint32_t a2, uint32_t a3,
                                         uint32_t b0, uint32_t b1) {
    asm volatile("mma.sync.aligned.m16n8k16.row.col.f32.bf16.bf16.f32 "
                 "{%0,%1,%2,%3}, {%4,%5,%6,%7}, {%8,%9}, {%0,%1,%2,%3};"
                 : "+f"(c[0]), "+f"(c[1]), "+f"(c[2]), "+f"(c[3])
                 : "r"(a0), "r"(a1), "r"(a2), "r"(a3), "r"(b0), "r"(b1));
}

#define KPAD 40   // bf16 elements per smem row (80B stride: odd word count -> conflict-free rows)

__global__ __launch_bounds__(256) void gemm_mma_kernel(const float* __restrict__ x,
                                                       float* __restrict__ out, int N)
{
    __shared__ unsigned short Ah[64][KPAD], Al[64][KPAD];
    __shared__ unsigned short Bh[128][KPAD], Bl[128][KPAD];
    int t = threadIdx.x, lane = t & 31, wid = t >> 5;
    int row0 = blockIdx.x * 64;
    int wr = (wid & 3) * 16;       // warp row base within CTA
    int wc = (wid >> 2) * 64;      // warp col base

    float acc[8][4];
#pragma unroll
    for (int i = 0; i < 8; i++)
#pragma unroll
        for (int j = 0; j < 4; j++) acc[i][j] = 0.f;

    for (int kk = 0; kk < 256; kk += 32) {
        // A tile: 64 rows x 32 bf16 (hi+lo), uint2 = 4 bf16 per load
#pragma unroll
        for (int it = 0; it < 2; it++) {
            int p = t + it * 256;        // 0..511
            int row = p >> 3, u = p & 7;
            int r = row0 + row;
            uint2 vh = make_uint2(0u, 0u), vl = make_uint2(0u, 0u);
            if (r < N) {
                size_t src = (size_t)r * 256 + kk + u * 4;
                vh = *(const uint2*)(g_Ah + src);
                vl = *(const uint2*)(g_Al + src);
            }
            *(uint2*)&Ah[row][u * 4] = vh;
            *(uint2*)&Al[row][u * 4] = vl;
        }
        // B tile: 128 rows x 32 bf16 (hi+lo)
#pragma unroll
        for (int it = 0; it < 4; it++) {
            int p = t + it * 256;        // 0..1023
            int j = p >> 3, u = p & 7;
            size_t src = (size_t)j * 256 + kk + u * 4;
            *(uint2*)&Bh[j][u * 4] = *(const uint2*)(g_Bh + src);
            *(uint2*)&Bl[j][u * 4] = *(const uint2*)(g_Bl + src);
        }
        __syncthreads();
#pragma unroll
        for (int ks = 0; ks < 32; ks += 16) {
            int kq = ks + (lane & 3) * 2;
            int ra = wr + (lane >> 2);
            uint32_t ah0 = *(const uint32_t*)&Ah[ra][kq];
            uint32_t ah1 = *(const uint32_t*)&Ah[ra + 8][kq];
            uint32_t ah2 = *(const uint32_t*)&Ah[ra][kq + 8];
            uint32_t ah3 = *(const uint32_t*)&Ah[ra + 8][kq + 8];
            uint32_t al0 = *(const uint32_t*)&Al[ra][kq];
            uint32_t al1 = *(const uint32_t*)&Al[ra + 8][kq];
            uint32_t al2 = *(const uint32_t*)&Al[ra][kq + 8];
            uint32_t al3 = *(const uint32_t*)&Al[ra + 8][kq + 8];
#pragma unroll
            for (int nt = 0; nt < 8; nt++) {
                int cb = wc + nt * 8 + (lane >> 2);
                uint32_t bh0 = *(const uint32_t*)&Bh[cb][kq];
                uint32_t bh1 = *(const uint32_t*)&Bh[cb][kq + 8];
                uint32_t bl0 = *(const uint32_t*)&Bl[cb][kq];
                uint32_t bl1 = *(const uint32_t*)&Bl[cb][kq + 8];
                mma_bf16(acc[nt], ah0, ah1, ah2, ah3, bh0, bh1);
                mma_bf16(acc[nt], al0, al1, al2, al3, bh0, bh1);
                mma_bf16(acc[nt], ah0, ah1, ah2, ah3, bl0, bl1);
            }
        }
        __syncthreads();
    }

    // epilogue: C frag (r, c)=(wr+lane/4, (lane%3)*2...) standard m16n8 mapping
    int r1 = row0 + wr + (lane >> 2);
    int r2 = r1 + 8;
#pragma unroll
    for (int nt = 0; nt < 8; nt++) {
        int col = wc + nt * 8 + (lane & 3) * 2;
        if (r1 < N) {
            float* o = out + (size_t)r1 * ROWLEN + col;
            o[0] = fmaxf(acc[nt][0], 0.f);
            o[1] = fmaxf(acc[nt][1], 0.f);
        }
        if (r2 < N) {
            float* o = out + (size_t)r2 * ROWLEN + col;
            o[0] = fmaxf(acc[nt][2], 0.f);
            o[1] = fmaxf(acc[nt][3], 0.f);
        }
    }
    if (t < 64) {
        int r = row0 + t;
        if (r < N) out[(size_t)r * ROWLEN + 128] = fmaxf(x[(size_t)r * ROWLEN + 128], 0.f);
    }
}

// ============================ launch ============================
extern "C" void kernel_launch(void* const* d_in, const int* in_sizes, int n_in,
                              void* d_out, int out_size) {
    const float* x  = (const float*)d_in[0];
    const int*   ei = (const int*)d_in[1];
    const float* Wn = (const float*)d_in[2];
    const float* Ws = (const float*)d_in[3];
    float* out = (float*)d_out;
    int N = in_sizes[0] / ROWLEN;
    int E = in_sizes[1] / 2;
    int nblk = (N + 255) / 256;

    zero_kernel<<<(N + 255) / 256, 256>>>(N);
    norms_kernel<<<(N + 7) / 8, 256>>>(x, N);
    hist_kernel<<<(E + 255) / 256, 256>>>(ei, E);
    scan_part_kernel<<<nblk, 256>>>(N);
    scan_mid_kernel<<<1, 256>>>(nblk);
    scan_final_kernel<<<nblk, 256>>>(N);
    scatter_kernel<<<(E + 255) / 256, 256>>>(ei, E);
    wconv_kernel<<<128, 256>>>(Wn, Ws);
    featconv_kernel<<<(N * 128 + 255) / 256, 256>>>(x, N);
    agg_kernel<<<(N + 7) / 8, 256>>>(x, N);
    gemm_mma_kernel<<<(N + 63) / 64, 256>>>(x, out, N);
}

// round 6
// speedup vs baseline: 2.0390x; 1.2048x over previous
#include <cuda_runtime.h>
#include <cuda_bf16.h>
#include <cstdint>

#define N_MAX 50000
#define E_MAX 640000
#define D 128
#define ROWLEN 129
#define EPSV 1e-9f
#define WMIN 1e-6f

// ---- static scratch ----
__device__ int   g_deg[N_MAX];
__device__ int   g_cursor[N_MAX];     // CSR write cursor / row starts
__device__ int   g_rowptr[N_MAX + 1];
__device__ int   g_col[E_MAX];
__device__ int   g_part[256];
// A = [neigh | feat] as double-bf16 split (hi, lo), row-major [N][256]
__device__ unsigned short g_Ah[(size_t)N_MAX * 256];
__device__ unsigned short g_Al[(size_t)N_MAX * 256];
// B rows j: [Wn[j,:] | Ws[j,:]] as split, [128][256]
__device__ unsigned short g_Bh[128 * 256];
__device__ unsigned short g_Bl[128 * 256];

__device__ __forceinline__ void split_bf16(float v, unsigned short& h, unsigned short& l) {
    __nv_bfloat16 hb = __float2bfloat16(v);
    float lo = v - __bfloat162float(hb);
    h = __bfloat16_as_ushort(hb);
    l = __bfloat16_as_ushort(__float2bfloat16(lo));
}

// ============================ fat kernel 1: hist + wconv ============================
__global__ void hist_wconv_kernel(const int* __restrict__ ei, int E, int hBlocks,
                                  const float* __restrict__ Wn, const float* __restrict__ Ws) {
    int b = blockIdx.x;
    if (b < hBlocks) {
        int e = b * 256 + threadIdx.x;
        if (e < E) atomicAdd(&g_deg[ei[e]], 1);
    } else {
        int j = b - hBlocks;            // 0..127
        int k = threadIdx.x;            // 0..255
        float v = (k < 128) ? Wn[j * 128 + k] : Ws[j * 128 + (k - 128)];
        split_bf16(v, g_Bh[j * 256 + k], g_Bl[j * 256 + k]);
    }
}

// ============================ scan: block sums, then final with inline mid ============================
__global__ void scan_part_kernel(int N) {
    __shared__ int ws[8];
    int t = threadIdx.x, b = blockIdx.x;
    int i = b * 256 + t;
    int v = (i < N) ? g_deg[i] : 0;
#pragma unroll
    for (int off = 16; off > 0; off >>= 1) v += __shfl_xor_sync(0xffffffffu, v, off);
    if ((t & 31) == 0) ws[t >> 5] = v;
    __syncthreads();
    if (t == 0) {
        int s = 0;
#pragma unroll
        for (int w = 0; w < 8; w++) s += ws[w];
        g_part[b] = s;
    }
}

__global__ void scan_final_kernel(int N, int nblk) {
    __shared__ int ws[8];
    __shared__ int boff;
    int t = threadIdx.x, b = blockIdx.x, lane = t & 31, w = t >> 5;

    // ---- block offset = sum of g_part[i] for i < b (inline "mid" scan) ----
    int pv = (t < b && t < nblk) ? g_part[t] : 0;
#pragma unroll
    for (int off = 16; off > 0; off >>= 1) pv += __shfl_xor_sync(0xffffffffu, pv, off);
    if (lane == 0) ws[w] = pv;
    __syncthreads();
    if (t == 0) {
        int s = 0;
#pragma unroll
        for (int ww = 0; ww < 8; ww++) s += ws[ww];
        boff = s;
    }
    __syncthreads();
    int blockOff = boff;
    __syncthreads();   // ws reused below

    // ---- per-block exclusive/inclusive scan of degrees ----
    int i = b * 256 + t;
    int v = (i < N) ? g_deg[i] : 0;
    int s = v;
#pragma unroll
    for (int off = 1; off < 32; off <<= 1) {
        int u = __shfl_up_sync(0xffffffffu, s, off);
        if (lane >= off) s += u;
    }
    if (lane == 31) ws[w] = s;
    __syncthreads();
    if (w == 0) {
        int p = (lane < 8) ? ws[lane] : 0;
#pragma unroll
        for (int off = 1; off < 8; off <<= 1) {
            int u = __shfl_up_sync(0xffffffffu, p, off);
            if (lane >= off) p += u;
        }
        if (lane < 8) ws[lane] = p;
    }
    __syncthreads();
    int incl = s + (w > 0 ? ws[w - 1] : 0);
    if (i < N) {
        g_rowptr[i + 1] = blockOff + incl;
        g_cursor[i]     = blockOff + incl - v;   // exclusive start = scatter cursor
    }
    if (b == 0 && t == 0) g_rowptr[0] = 0;
}

__global__ void scatter_kernel(const int* __restrict__ ei, int E) {
    int e = blockIdx.x * blockDim.x + threadIdx.x;
    if (e < E) {
        int r = ei[e];
        int c = ei[E + e];
        int pos = atomicAdd(&g_cursor[r], 1);
        g_col[pos] = c;
    }
}

// ============================ aggregation (warp per row) ============================
// Fuses: inline norms (both endpoints), edge weights, weighted mean, and the
// bf16 hi/lo split write of BOTH halves of A (neigh cols 0-127, feat cols 128-255).
__global__ void agg_kernel(const float* __restrict__ x, int N) {
    int warp = (blockIdx.x * blockDim.x + threadIdx.x) >> 5;
    int lane = threadIdx.x & 31;
    if (warp >= N) return;
    int r = warp;
    const float* xr = x + (size_t)r * ROWLEN;
    float xr0 = xr[lane], xr1 = xr[lane + 32], xr2 = xr[lane + 64], xr3 = xr[lane + 96];
    float xrh = xr[128];

    // inline norm of own feature row (same per-lane + butterfly order as before)
    float nr = xr0 * xr0 + xr1 * xr1 + xr2 * xr2 + xr3 * xr3;
#pragma unroll
    for (int off = 16; off > 0; off >>= 1) nr += __shfl_xor_sync(0xffffffffu, nr, off);
    nr += EPSV;

    float acc0 = 0.f, acc1 = 0.f, acc2 = 0.f, acc3 = 0.f, wsum = 0.f;
    int jb = g_rowptr[r], je = g_rowptr[r + 1];
#pragma unroll 2
    for (int j = jb; j < je; j++) {
        int c = g_col[j];
        const float* xc = x + (size_t)c * ROWLEN;
        float c0 = xc[lane], c1 = xc[lane + 32], c2 = xc[lane + 64], c3 = xc[lane + 96];
        float part = xr0 * c0 + xr1 * c1 + xr2 * c2 + xr3 * c3;
        if (lane == 0) part += xrh * xc[128];
        float nc = c0 * c0 + c1 * c1 + c2 * c2 + c3 * c3;
        // two independent butterfly chains: latencies overlap
#pragma unroll
        for (int off = 16; off > 0; off >>= 1) {
            part += __shfl_xor_sync(0xffffffffu, part, off);
            nc   += __shfl_xor_sync(0xffffffffu, nc, off);
        }
        float w = __expf(part * part / (nr * (nc + EPSV)) - 1.0f);
        acc0 += w * c0; acc1 += w * c1; acc2 += w * c2; acc3 += w * c3;
        wsum += w;
    }
    float inv = 1.0f / fmaxf(wsum, WMIN);
    size_t base = (size_t)r * 256;
    // neigh half
    split_bf16(acc0 * inv, g_Ah[base + lane],      g_Al[base + lane]);
    split_bf16(acc1 * inv, g_Ah[base + lane + 32], g_Al[base + lane + 32]);
    split_bf16(acc2 * inv, g_Ah[base + lane + 64], g_Al[base + lane + 64]);
    split_bf16(acc3 * inv, g_Ah[base + lane + 96], g_Al[base + lane + 96]);
    // feat half (fused featconv)
    split_bf16(xr0, g_Ah[base + 128 + lane],      g_Al[base + 128 + lane]);
    split_bf16(xr1, g_Ah[base + 128 + lane + 32], g_Al[base + 128 + lane + 32]);
    split_bf16(xr2, g_Ah[base + 128 + lane + 64], g_Al[base + 128 + lane + 64]);
    split_bf16(xr3, g_Ah[base + 128 + lane + 96], g_Al[base + 128 + lane + 96]);
}

// ============================ mma.sync bf16 GEMM + relu + concat ============================
__device__ __forceinline__ void mma_bf16(float* c, uint32_t a0, uint32_t a1, uint32_t a2, uint32_t a3,
                                         uint32_t b0, uint32_t b1) {
    asm volatile("mma.sync.aligned.m16n8k16.row.col.f32.bf16.bf16.f32 "
                 "{%0,%1,%2,%3}, {%4,%5,%6,%7}, {%8,%9}, {%0,%1,%2,%3};"
                 : "+f"(c[0]), "+f"(c[1]), "+f"(c[2]), "+f"(c[3])
                 : "r"(a0), "r"(a1), "r"(a2), "r"(a3), "r"(b0), "r"(b1));
}

#define KPAD 40

__global__ __launch_bounds__(256) void gemm_mma_kernel(const float* __restrict__ x,
                                                       float* __restrict__ out, int N)
{
    __shared__ unsigned short Ah[64][KPAD], Al[64][KPAD];
    __shared__ unsigned short Bh[128][KPAD], Bl[128][KPAD];
    int t = threadIdx.x, lane = t & 31, wid = t >> 5;
    int row0 = blockIdx.x * 64;
    int wr = (wid & 3) * 16;
    int wc = (wid >> 2) * 64;

    float acc[8][4];
#pragma unroll
    for (int i = 0; i < 8; i++)
#pragma unroll
        for (int j = 0; j < 4; j++) acc[i][j] = 0.f;

    for (int kk = 0; kk < 256; kk += 32) {
#pragma unroll
        for (int it = 0; it < 2; it++) {
            int p = t + it * 256;
            int row = p >> 3, u = p & 7;
            int r = row0 + row;
            uint2 vh = make_uint2(0u, 0u), vl = make_uint2(0u, 0u);
            if (r < N) {
                size_t src = (size_t)r * 256 + kk + u * 4;
                vh = *(const uint2*)(g_Ah + src);
                vl = *(const uint2*)(g_Al + src);
            }
            *(uint2*)&Ah[row][u * 4] = vh;
            *(uint2*)&Al[row][u * 4] = vl;
        }
#pragma unroll
        for (int it = 0; it < 4; it++) {
            int p = t + it * 256;
            int j = p >> 3, u = p & 7;
            size_t src = (size_t)j * 256 + kk + u * 4;
            *(uint2*)&Bh[j][u * 4] = *(const uint2*)(g_Bh + src);
            *(uint2*)&Bl[j][u * 4] = *(const uint2*)(g_Bl + src);
        }
        __syncthreads();
#pragma unroll
        for (int ks = 0; ks < 32; ks += 16) {
            int kq = ks + (lane & 3) * 2;
            int ra = wr + (lane >> 2);
            uint32_t ah0 = *(const uint32_t*)&Ah[ra][kq];
            uint32_t ah1 = *(const uint32_t*)&Ah[ra + 8][kq];
            uint32_t ah2 = *(const uint32_t*)&Ah[ra][kq + 8];
            uint32_t ah3 = *(const uint32_t*)&Ah[ra + 8][kq + 8];
            uint32_t al0 = *(const uint32_t*)&Al[ra][kq];
            uint32_t al1 = *(const uint32_t*)&Al[ra + 8][kq];
            uint32_t al2 = *(const uint32_t*)&Al[ra][kq + 8];
            uint32_t al3 = *(const uint32_t*)&Al[ra + 8][kq + 8];
#pragma unroll
            for (int nt = 0; nt < 8; nt++) {
                int cb = wc + nt * 8 + (lane >> 2);
                uint32_t bh0 = *(const uint32_t*)&Bh[cb][kq];
                uint32_t bh1 = *(const uint32_t*)&Bh[cb][kq + 8];
                uint32_t bl0 = *(const uint32_t*)&Bl[cb][kq];
                uint32_t bl1 = *(const uint32_t*)&Bl[cb][kq + 8];
                mma_bf16(acc[nt], ah0, ah1, ah2, ah3, bh0, bh1);
                mma_bf16(acc[nt], al0, al1, al2, al3, bh0, bh1);
                mma_bf16(acc[nt], ah0, ah1, ah2, ah3, bl0, bl1);
            }
        }
        __syncthreads();
    }

    int r1 = row0 + wr + (lane >> 2);
    int r2 = r1 + 8;
#pragma unroll
    for (int nt = 0; nt < 8; nt++) {
        int col = wc + nt * 8 + (lane & 3) * 2;
        if (r1 < N) {
            float* o = out + (size_t)r1 * ROWLEN + col;
            o[0] = fmaxf(acc[nt][0], 0.f);
            o[1] = fmaxf(acc[nt][1], 0.f);
        }
        if (r2 < N) {
            float* o = out + (size_t)r2 * ROWLEN + col;
            o[0] = fmaxf(acc[nt][2], 0.f);
            o[1] = fmaxf(acc[nt][3], 0.f);
        }
    }
    if (t < 64) {
        int r = row0 + t;
        if (r < N) out[(size_t)r * ROWLEN + 128] = fmaxf(x[(size_t)r * ROWLEN + 128], 0.f);
    }
}

// ============================ launch ============================
extern "C" void kernel_launch(void* const* d_in, const int* in_sizes, int n_in,
                              void* d_out, int out_size) {
    const float* x  = (const float*)d_in[0];
    const int*   ei = (const int*)d_in[1];
    const float* Wn = (const float*)d_in[2];
    const float* Ws = (const float*)d_in[3];
    float* out = (float*)d_out;
    int N = in_sizes[0] / ROWLEN;
    int E = in_sizes[1] / 2;
    int nblk = (N + 255) / 256;
    int hBlocks = (E + 255) / 256;

    void* degPtr = nullptr;
    cudaGetSymbolAddress(&degPtr, g_deg);
    cudaMemsetAsync(degPtr, 0, (size_t)N * sizeof(int));

    hist_wconv_kernel<<<hBlocks + 128, 256>>>(ei, E, hBlocks, Wn, Ws);
    scan_part_kernel<<<nblk, 256>>>(N);
    scan_final_kernel<<<nblk, 256>>>(N, nblk);
    scatter_kernel<<<hBlocks, 256>>>(ei, E);
    agg_kernel<<<(N + 7) / 8, 256>>>(x, N);
    gemm_mma_kernel<<<(N + 63) / 64, 256>>>(x, out, N);
}